// round 2
// baseline (speedup 1.0000x reference)
#include <cuda_runtime.h>
#include <cuda_bf16.h>

// GANLoss: out = -mean(prob[n, targets[n]] * reward[n]), N=8192, C=32000.
// Latency-bound scatter-gather: 8192 random 4B reads from a 1GB matrix.
// Two-kernel deterministic tree reduction (no float atomics).
// NOTE: targets are int32 (JAX x64 disabled downgrades jnp.int64 -> int32).

#define NBLOCKS 32
#define NTHREADS 256

__device__ float g_partials[NBLOCKS];

__global__ __launch_bounds__(NTHREADS) void gather_partial_kernel(
    const float* __restrict__ prob,
    const int* __restrict__ targets,
    const float* __restrict__ reward,
    int N, long long C)
{
    int idx = blockIdx.x * blockDim.x + threadIdx.x;

    float v = 0.0f;
    if (idx < N) {
        int t = targets[idx];
        v = __ldg(&prob[(long long)idx * C + (long long)t]) * __ldg(&reward[idx]);
    }

    // warp reduce
    #pragma unroll
    for (int off = 16; off > 0; off >>= 1)
        v += __shfl_xor_sync(0xFFFFFFFFu, v, off);

    __shared__ float s_warp[NTHREADS / 32];
    int lane = threadIdx.x & 31;
    int wid  = threadIdx.x >> 5;
    if (lane == 0) s_warp[wid] = v;
    __syncthreads();

    if (wid == 0) {
        float w = (lane < NTHREADS / 32) ? s_warp[lane] : 0.0f;
        #pragma unroll
        for (int off = 4; off > 0; off >>= 1)
            w += __shfl_xor_sync(0xFFFFFFFFu, w, off);
        if (lane == 0) g_partials[blockIdx.x] = w;
    }
}

__global__ void finalize_kernel(float* __restrict__ out, float inv_n)
{
    // one warp: NBLOCKS == 32 partials
    float v = g_partials[threadIdx.x];
    #pragma unroll
    for (int off = 16; off > 0; off >>= 1)
        v += __shfl_xor_sync(0xFFFFFFFFu, v, off);
    if (threadIdx.x == 0)
        out[0] = -v * inv_n;
}

extern "C" void kernel_launch(void* const* d_in, const int* in_sizes, int n_in,
                              void* d_out, int out_size)
{
    const float* prob    = (const float*)d_in[0];
    const int*   targets = (const int*)d_in[1];
    const float* reward  = (const float*)d_in[2];
    float*       out     = (float*)d_out;

    const int N = in_sizes[2];                       // 8192 (reward element count)
    const long long C = (long long)in_sizes[0] / N;  // 32000

    gather_partial_kernel<<<NBLOCKS, NTHREADS>>>(prob, targets, reward, N, C);
    finalize_kernel<<<1, 32>>>(out, 1.0f / (float)N);
}